// round 1
// baseline (speedup 1.0000x reference)
#include <cuda_runtime.h>
#include <cuda_bf16.h>
#include <math.h>

// Problem constants
#define BB     64
#define TT     2048
#define HH     512
#define UNITS  128
#define SSPLIT 32           // T-splits for the main pass
#define ROWS_PER_BLOCK (TT / SSPLIT)   // 64
#define WARPS_PER_BLOCK 8
#define ROWS_PER_WARP (ROWS_PER_BLOCK / WARPS_PER_BLOCK) // 8

// Scratch (allocation-free rule: __device__ globals)
__device__ float g_v[BB * HH];                       // v[b,h] = (W_score @ h_t)[h]
__device__ float g_part[BB * SSPLIT * (HH + 2)];     // per-(b,split): m, l, acc[512]

// ---------------------------------------------------------------------------
// Kernel A: v[b,h] = sum_k W_score[h,k] * hidden[b, T-1, k]
// grid(BB, HH/8), block 256 (8 warps, one output row each)
// ---------------------------------------------------------------------------
__global__ void compute_v_kernel(const float* __restrict__ hidden,
                                 const float* __restrict__ Wscore) {
    int b = blockIdx.x;
    int g = blockIdx.y;                 // 0..63
    __shared__ float sht[HH];
    const float* ht = hidden + ((size_t)b * TT + (TT - 1)) * HH;
    for (int i = threadIdx.x; i < HH; i += blockDim.x) sht[i] = ht[i];
    __syncthreads();

    int w = threadIdx.x >> 5;
    int lane = threadIdx.x & 31;
    int h = g * 8 + w;
    const float* Wr = Wscore + (size_t)h * HH;
    float sum = 0.f;
#pragma unroll 4
    for (int i = lane; i < HH; i += 32) sum += Wr[i] * sht[i];
#pragma unroll
    for (int o = 16; o; o >>= 1) sum += __shfl_xor_sync(0xffffffffu, sum, o);
    if (lane == 0) g_v[b * HH + h] = sum;
}

// ---------------------------------------------------------------------------
// Kernel B: single streaming pass over hidden with online softmax.
// Each warp handles ROWS_PER_WARP rows, keeps (m, l, acc[16 floats/lane]).
// grid(SSPLIT, BB), block 256.
// ---------------------------------------------------------------------------
__global__ void __launch_bounds__(256) pass_kernel(const float* __restrict__ hidden) {
    int s = blockIdx.x;
    int b = blockIdx.y;
    int w = threadIdx.x >> 5;
    int lane = threadIdx.x & 31;

    __shared__ float4 sv[HH / 4];        // v[b], 2 KB
    __shared__ float  sm[WARPS_PER_BLOCK];
    __shared__ float  sl[WARPS_PER_BLOCK];
    __shared__ float4 sacc[WARPS_PER_BLOCK * (HH / 4)]; // 16 KB

    const float4* v4 = (const float4*)(g_v + (size_t)b * HH);
    for (int i = threadIdx.x; i < HH / 4; i += 256) sv[i] = v4[i];
    __syncthreads();

    int t0 = s * ROWS_PER_BLOCK + w * ROWS_PER_WARP;

    float m = -1e30f, l = 0.f;
    float acc[16];
#pragma unroll
    for (int i = 0; i < 16; i++) acc[i] = 0.f;

    for (int r = 0; r < ROWS_PER_WARP; r++) {
        int t = t0 + r;
        const float4* row4 = (const float4*)(hidden + ((size_t)b * TT + t) * HH);
        float4 x[4];
        float sdot = 0.f;
#pragma unroll
        for (int c = 0; c < 4; c++) {
            x[c] = row4[c * 32 + lane];
            float4 vv = sv[c * 32 + lane];
            sdot += x[c].x * vv.x + x[c].y * vv.y + x[c].z * vv.z + x[c].w * vv.w;
        }
#pragma unroll
        for (int o = 16; o; o >>= 1) sdot += __shfl_xor_sync(0xffffffffu, sdot, o);

        float nm = fmaxf(m, sdot);
        float sc = __expf(m - nm);
        float e  = __expf(sdot - nm);
        m = nm;
        l = l * sc + e;
#pragma unroll
        for (int c = 0; c < 4; c++) {
            acc[4 * c + 0] = acc[4 * c + 0] * sc + e * x[c].x;
            acc[4 * c + 1] = acc[4 * c + 1] * sc + e * x[c].y;
            acc[4 * c + 2] = acc[4 * c + 2] * sc + e * x[c].z;
            acc[4 * c + 3] = acc[4 * c + 3] * sc + e * x[c].w;
        }
    }

    if (lane == 0) { sm[w] = m; sl[w] = l; }
#pragma unroll
    for (int c = 0; c < 4; c++) {
        float4 a4 = make_float4(acc[4 * c + 0], acc[4 * c + 1],
                                acc[4 * c + 2], acc[4 * c + 3]);
        sacc[w * (HH / 4) + c * 32 + lane] = a4;
    }
    __syncthreads();

    // Combine the 8 warps' online-softmax states (all threads recompute the same M/L)
    float M = sm[0];
#pragma unroll
    for (int ww = 1; ww < WARPS_PER_BLOCK; ww++) M = fmaxf(M, sm[ww]);
    float L = 0.f;
    float wscale[WARPS_PER_BLOCK];
#pragma unroll
    for (int ww = 0; ww < WARPS_PER_BLOCK; ww++) {
        wscale[ww] = __expf(sm[ww] - M);
        L += sl[ww] * wscale[ww];
    }

    float* outp = g_part + ((size_t)(b * SSPLIT + s)) * (HH + 2);
    const float* saccf = (const float*)sacc;
    for (int h = threadIdx.x; h < HH; h += 256) {
        float a = 0.f;
#pragma unroll
        for (int ww = 0; ww < WARPS_PER_BLOCK; ww++)
            a += saccf[ww * HH + h] * wscale[ww];
        outp[2 + h] = a;
    }
    if (threadIdx.x == 0) { outp[0] = M; outp[1] = L; }
}

// ---------------------------------------------------------------------------
// Kernel C: merge split partials -> context, then [ctx | h_t] @ W_out, tanh.
// grid(BB), block 256 (first 128 threads compute the 128 outputs).
// ---------------------------------------------------------------------------
__global__ void finalize_kernel(const float* __restrict__ hidden,
                                const float* __restrict__ Wout,
                                float* __restrict__ out) {
    int b = blockIdx.x;
    int tid = threadIdx.x;
    __shared__ float sctx[HH];
    __shared__ float sht[HH];
    __shared__ float sMs[SSPLIT];
    __shared__ float sLs[SSPLIT];

    if (tid < SSPLIT) {
        const float* p = g_part + ((size_t)(b * SSPLIT + tid)) * (HH + 2);
        sMs[tid] = p[0];
        sLs[tid] = p[1];
    }
    __syncthreads();

    float M = sMs[0];
#pragma unroll
    for (int s = 1; s < SSPLIT; s++) M = fmaxf(M, sMs[s]);
    float L = 0.f;
#pragma unroll
    for (int s = 0; s < SSPLIT; s++) L += sLs[s] * __expf(sMs[s] - M);
    float invL = 1.f / L;

    for (int h = tid; h < HH; h += blockDim.x) {
        float a = 0.f;
#pragma unroll 4
        for (int s = 0; s < SSPLIT; s++) {
            const float* p = g_part + ((size_t)(b * SSPLIT + s)) * (HH + 2);
            a += p[2 + h] * __expf(sMs[s] - M);
        }
        sctx[h] = a * invL;
    }
    const float* ht = hidden + ((size_t)b * TT + (TT - 1)) * HH;
    for (int h = tid; h < HH; h += blockDim.x) sht[h] = ht[h];
    __syncthreads();

    if (tid < UNITS) {
        float sum = 0.f;
#pragma unroll 8
        for (int r = 0; r < HH; r++)
            sum += sctx[r] * Wout[(size_t)r * UNITS + tid];
#pragma unroll 8
        for (int r = 0; r < HH; r++)
            sum += sht[r] * Wout[(size_t)(HH + r) * UNITS + tid];
        out[b * UNITS + tid] = tanhf(sum);
    }
}

// ---------------------------------------------------------------------------
extern "C" void kernel_launch(void* const* d_in, const int* in_sizes, int n_in,
                              void* d_out, int out_size) {
    const float* hidden = (const float*)d_in[0];   // (B, T, H)
    const float* Wscore = (const float*)d_in[1];   // (H, H)
    const float* Wout   = (const float*)d_in[2];   // (2H, UNITS)
    float* out = (float*)d_out;                    // (B, UNITS)

    dim3 gA(BB, HH / 8);
    compute_v_kernel<<<gA, 256>>>(hidden, Wscore);

    dim3 gB(SSPLIT, BB);
    pass_kernel<<<gB, 256>>>(hidden);

    finalize_kernel<<<BB, 256>>>(hidden, Wout, out);
}

// round 2
// speedup vs baseline: 1.8501x; 1.8501x over previous
#include <cuda_runtime.h>
#include <cuda_bf16.h>
#include <math.h>

// Problem constants
#define BB     64
#define TT     2048
#define HH     512
#define UNITS  128
#define SSPLIT 32                       // T-splits for the main pass
#define ROWS_PER_BLOCK (TT / SSPLIT)    // 64
#define WARPS_PER_BLOCK 8
#define ROWS_PER_WARP (ROWS_PER_BLOCK / WARPS_PER_BLOCK) // 8

// Scratch (allocation-free rule: __device__ globals)
__device__ float g_v[BB * HH];                       // v[b,h] = (W_score @ h_t)[h]
__device__ float g_part[BB * SSPLIT * (HH + 2)];     // per-(b,split): m, l, acc[512]

// ---------------------------------------------------------------------------
// Kernel A: v[b,h] = sum_k W_score[h,k] * h_t[b,k]
// grid(BB, 8), block 256. Warp w handles 8 rows h = g*64 + w*8 + r,
// 2 rows interleaved per step for MLP and overlapped shuffle chains.
// ---------------------------------------------------------------------------
__global__ void __launch_bounds__(256) compute_v_kernel(
        const float* __restrict__ hidden, const float* __restrict__ Wscore) {
    int b = blockIdx.x;
    int g = blockIdx.y;                 // 0..7
    __shared__ float4 sht[HH / 4];
    const float4* ht4 = (const float4*)(hidden + ((size_t)b * TT + (TT - 1)) * HH);
    for (int i = threadIdx.x; i < HH / 4; i += 256) sht[i] = ht4[i];
    __syncthreads();

    int w = threadIdx.x >> 5;
    int lane = threadIdx.x & 31;
    int h0 = g * 64 + w * 8;

#pragma unroll
    for (int r = 0; r < 8; r += 2) {
        const float4* W0 = (const float4*)(Wscore + (size_t)(h0 + r) * HH);
        const float4* W1 = (const float4*)(Wscore + (size_t)(h0 + r + 1) * HH);
        float s0 = 0.f, s1 = 0.f;
#pragma unroll
        for (int c = 0; c < 4; c++) {
            float4 a = W0[c * 32 + lane];
            float4 d = W1[c * 32 + lane];
            float4 vv = sht[c * 32 + lane];
            s0 += a.x * vv.x + a.y * vv.y + a.z * vv.z + a.w * vv.w;
            s1 += d.x * vv.x + d.y * vv.y + d.z * vv.z + d.w * vv.w;
        }
#pragma unroll
        for (int o = 16; o; o >>= 1) {
            s0 += __shfl_xor_sync(0xffffffffu, s0, o);
            s1 += __shfl_xor_sync(0xffffffffu, s1, o);
        }
        if (lane == 0) {
            g_v[b * HH + h0 + r]     = s0;
            g_v[b * HH + h0 + r + 1] = s1;
        }
    }
}

// ---------------------------------------------------------------------------
// Kernel B: streaming pass over hidden with online softmax, 2 rows per step.
// grid(SSPLIT, BB), block 256 (8 warps, 8 rows each).
// ---------------------------------------------------------------------------
__global__ void __launch_bounds__(256) pass_kernel(const float* __restrict__ hidden) {
    int s = blockIdx.x;
    int b = blockIdx.y;
    int w = threadIdx.x >> 5;
    int lane = threadIdx.x & 31;

    __shared__ float4 sv[HH / 4];        // v[b], 2 KB
    __shared__ float  sm[WARPS_PER_BLOCK];
    __shared__ float  sl[WARPS_PER_BLOCK];
    __shared__ float4 sacc[WARPS_PER_BLOCK * (HH / 4)]; // 16 KB

    const float4* v4 = (const float4*)(g_v + (size_t)b * HH);
    for (int i = threadIdx.x; i < HH / 4; i += 256) sv[i] = v4[i];
    __syncthreads();

    int t0 = s * ROWS_PER_BLOCK + w * ROWS_PER_WARP;

    float m = -1e30f, l = 0.f;
    float acc[16];
#pragma unroll
    for (int i = 0; i < 16; i++) acc[i] = 0.f;

    for (int r = 0; r < ROWS_PER_WARP; r += 2) {
        const float4* row0 = (const float4*)(hidden + ((size_t)b * TT + t0 + r) * HH);
        const float4* row1 = (const float4*)(hidden + ((size_t)b * TT + t0 + r + 1) * HH);
        float4 x0[4], x1[4];
        float d0 = 0.f, d1 = 0.f;
#pragma unroll
        for (int c = 0; c < 4; c++) {
            x0[c] = row0[c * 32 + lane];
            x1[c] = row1[c * 32 + lane];
        }
#pragma unroll
        for (int c = 0; c < 4; c++) {
            float4 vv = sv[c * 32 + lane];
            d0 += x0[c].x * vv.x + x0[c].y * vv.y + x0[c].z * vv.z + x0[c].w * vv.w;
            d1 += x1[c].x * vv.x + x1[c].y * vv.y + x1[c].z * vv.z + x1[c].w * vv.w;
        }
#pragma unroll
        for (int o = 16; o; o >>= 1) {
            d0 += __shfl_xor_sync(0xffffffffu, d0, o);
            d1 += __shfl_xor_sync(0xffffffffu, d1, o);
        }

        float nm = fmaxf(m, fmaxf(d0, d1));
        float e0 = __expf(d0 - nm);
        float e1 = __expf(d1 - nm);
        if (nm == m) {                   // warp-uniform: max unchanged, no rescale
            l += e0 + e1;
#pragma unroll
            for (int c = 0; c < 4; c++) {
                acc[4 * c + 0] += e0 * x0[c].x + e1 * x1[c].x;
                acc[4 * c + 1] += e0 * x0[c].y + e1 * x1[c].y;
                acc[4 * c + 2] += e0 * x0[c].z + e1 * x1[c].z;
                acc[4 * c + 3] += e0 * x0[c].w + e1 * x1[c].w;
            }
        } else {
            float sc = __expf(m - nm);
            m = nm;
            l = l * sc + e0 + e1;
#pragma unroll
            for (int c = 0; c < 4; c++) {
                acc[4 * c + 0] = acc[4 * c + 0] * sc + e0 * x0[c].x + e1 * x1[c].x;
                acc[4 * c + 1] = acc[4 * c + 1] * sc + e0 * x0[c].y + e1 * x1[c].y;
                acc[4 * c + 2] = acc[4 * c + 2] * sc + e0 * x0[c].z + e1 * x1[c].z;
                acc[4 * c + 3] = acc[4 * c + 3] * sc + e0 * x0[c].w + e1 * x1[c].w;
            }
        }
    }

    if (lane == 0) { sm[w] = m; sl[w] = l; }
#pragma unroll
    for (int c = 0; c < 4; c++) {
        sacc[w * (HH / 4) + c * 32 + lane] =
            make_float4(acc[4 * c + 0], acc[4 * c + 1], acc[4 * c + 2], acc[4 * c + 3]);
    }
    __syncthreads();

    // Combine the 8 warps' online-softmax states
    float M = sm[0];
#pragma unroll
    for (int ww = 1; ww < WARPS_PER_BLOCK; ww++) M = fmaxf(M, sm[ww]);
    float L = 0.f;
    float wscale[WARPS_PER_BLOCK];
#pragma unroll
    for (int ww = 0; ww < WARPS_PER_BLOCK; ww++) {
        wscale[ww] = __expf(sm[ww] - M);
        L += sl[ww] * wscale[ww];
    }

    float* outp = g_part + ((size_t)(b * SSPLIT + s)) * (HH + 2);
    const float* saccf = (const float*)sacc;
    for (int h = threadIdx.x; h < HH; h += 256) {
        float a = 0.f;
#pragma unroll
        for (int ww = 0; ww < WARPS_PER_BLOCK; ww++)
            a += saccf[ww * HH + h] * wscale[ww];
        outp[2 + h] = a;
    }
    if (threadIdx.x == 0) { outp[0] = M; outp[1] = L; }
}

// ---------------------------------------------------------------------------
// Kernel C: merge split partials -> context, then [ctx | h_t] @ W_out, tanh.
// grid(BB), block 512. GEMM phase: 4 threads per output unit (r-split).
// ---------------------------------------------------------------------------
__global__ void __launch_bounds__(512) finalize_kernel(
        const float* __restrict__ hidden, const float* __restrict__ Wout,
        float* __restrict__ out) {
    int b = blockIdx.x;
    int tid = threadIdx.x;
    __shared__ float sIn[2 * HH];        // [ctx | h_t]
    __shared__ float sMs[SSPLIT];
    __shared__ float sLs[SSPLIT];
    __shared__ float sw[SSPLIT];
    __shared__ float spart[4][UNITS];

    if (tid < SSPLIT) {
        const float* p = g_part + ((size_t)(b * SSPLIT + tid)) * (HH + 2);
        sMs[tid] = p[0];
        sLs[tid] = p[1];
    }
    __syncthreads();

    float M = sMs[0];
#pragma unroll
    for (int s = 1; s < SSPLIT; s++) M = fmaxf(M, sMs[s]);
    float L = 0.f;
#pragma unroll
    for (int s = 0; s < SSPLIT; s++) L += sLs[s] * __expf(sMs[s] - M);
    float invL = 1.f / L;
    if (tid < SSPLIT) sw[tid] = __expf(sMs[tid] - M);
    __syncthreads();

    // merge: one thread per h (512 threads exactly)
    {
        int h = tid;
        float a = 0.f;
#pragma unroll 8
        for (int s = 0; s < SSPLIT; s++)
            a += g_part[((size_t)(b * SSPLIT + s)) * (HH + 2) + 2 + h] * sw[s];
        sIn[h] = a * invL;
        sIn[HH + h] = hidden[((size_t)b * TT + (TT - 1)) * HH + h];
    }
    __syncthreads();

    // GEMM: group g (0..3) covers r in [g*256, g*256+256), unit u = tid & 127
    {
        int grp = tid >> 7;
        int u = tid & 127;
        const float* Wp = Wout + (size_t)(grp * 256) * UNITS + u;
        const float* ip = sIn + grp * 256;
        float s0 = 0.f, s1 = 0.f;
#pragma unroll 8
        for (int r = 0; r < 256; r += 2) {
            s0 += ip[r]     * Wp[(size_t)r * UNITS];
            s1 += ip[r + 1] * Wp[(size_t)(r + 1) * UNITS];
        }
        spart[grp][u] = s0 + s1;
    }
    __syncthreads();

    if (tid < UNITS) {
        float sum = spart[0][tid] + spart[1][tid] + spart[2][tid] + spart[3][tid];
        out[b * UNITS + tid] = tanhf(sum);
    }
}

// ---------------------------------------------------------------------------
extern "C" void kernel_launch(void* const* d_in, const int* in_sizes, int n_in,
                              void* d_out, int out_size) {
    const float* hidden = (const float*)d_in[0];   // (B, T, H)
    const float* Wscore = (const float*)d_in[1];   // (H, H)
    const float* Wout   = (const float*)d_in[2];   // (2H, UNITS)
    float* out = (float*)d_out;                    // (B, UNITS)

    dim3 gA(BB, 8);
    compute_v_kernel<<<gA, 256>>>(hidden, Wscore);

    dim3 gB(SSPLIT, BB);
    pass_kernel<<<gB, 256>>>(hidden);

    finalize_kernel<<<BB, 512>>>(hidden, Wout, out);
}